// round 17
// baseline (speedup 1.0000x reference)
#include <cuda_runtime.h>

#define NB    4096
#define MAXKV 64
#define CTA   128            // 4 warps/CTA, warp per logical block
#define GRID  (NB / 4)       // 1024 CTAs; 7/SM -> fully co-resident (barrier-safe)

// Cross-CTA state. Only g_pk crosses the barrier; counters reset by last CTA.
__device__ float2 g_pk[NB];     // (Σ p·keep, Σ keep) published per block
__device__ float4 g_cta[GRID];  // per-CTA partials (bce, sup, gl, val)
__device__ int    g_bar;        // grid-barrier arrivals   (zero-init)
__device__ int    g_flag;       // grid-barrier release    (zero-init)
__device__ int    g_done;       // last-CTA-done counter   (zero-init)

__device__ __forceinline__ float warp_sum(float v) {
#pragma unroll
    for (int o = 16; o > 0; o >>= 1) v += __shfl_down_sync(0xffffffffu, v, o);
    return v;
}

__device__ __forceinline__ float tanh_fast(float x) {
    float r;
    asm("tanh.approx.f32 %0, %1;" : "=f"(r) : "f"(x));
    return r;
}

__global__ void __launch_bounds__(CTA) fused(const float4* __restrict__ x4,
                                             const float4* __restrict__ t4,
                                             const uint4*  __restrict__ s4,
                                             const uint4*  __restrict__ i4,
                                             const uint2*  __restrict__ kvi2,
                                             const int*    __restrict__ kvn,
                                             float* __restrict__ out) {
    const int tid  = threadIdx.x;
    const int lane = tid & 31;
    const int wid  = tid >> 5;
    const int b    = blockIdx.x * 4 + wid;   // logical block
    const int vidx = b * 32 + lane;

    // ---- Front-batched loads: phase-B metadata + phase-A data (6 independent LDGs) ----
    const uint2  jj = kvi2[vidx];            // neighbors 2*lane, 2*lane+1
    const int    nb = kvn[b];
    const float4 xv = x4[vidx];
    const float4 tv = t4[vidx];
    const uint4  sv = s4[vidx];
    const uint4  iv = i4[vidx];

    // ---- Phase A: per-node math; per-block scalars stay in REGISTERS ----
    float bce_s = 0.f, pk_s = 0.f, p1 = 0.f, p2 = 0.f;
    unsigned cnt_s = 0, cnt_k = 0, cnt_q = 0;
    {
        const float xs[4] = {xv.x, xv.y, xv.z, xv.w};
        const float ts[4] = {tv.x, tv.y, tv.z, tv.w};
        const unsigned int ss[4] = {sv.x, sv.y, sv.z, sv.w};
        const unsigned int is[4] = {iv.x, iv.y, iv.z, iv.w};
#pragma unroll
        for (int k = 0; k < 4; k++) {
            const float x  = xs[k];
            const float ax = fabsf(x);
            const float pp = fmaf(0.5f, tanh_fast(0.5f * ax), 0.5f);  // sigmoid(|x|)
            const float sp = fmaxf(x, 0.0f) - __logf(pp);             // softplus
            const float p  = (x >= 0.0f) ? pp : (1.0f - pp);          // sigmoid(x)
            const bool s    = ss[k] != 0u;
            const bool keep = is[k] == 0u;
            const bool unc  = keep && !s;
            cnt_s += __popc(__ballot_sync(0xffffffffu, s));
            cnt_k += __popc(__ballot_sync(0xffffffffu, keep));
            cnt_q += __popc(__ballot_sync(0xffffffffu, unc));
            if (s)    { bce_s += sp - ts[k] * x; }
            if (keep) { pk_s  += p; }
            if (unc)  { p1 += p; p2 += p * p; }
        }
    }
    bce_s = warp_sum(bce_s);
    pk_s  = warp_sum(pk_s);
    p1    = warp_sum(p1);
    p2    = warp_sum(p2);

    // Publish ONLY the cross-CTA pair.
    if (lane == 0) g_pk[b] = make_float2(pk_s, (float)cnt_k);

    // ---- Grid barrier (all 1024 CTAs resident; light uniform phases -> small spread) ----
    __syncthreads();
    if (tid == 0) {
        __threadfence();                                   // release g_pk
        if (atomicAdd(&g_bar, 1) == GRID - 1) {
            atomicExch(&g_flag, 1);
        } else {
            volatile int* vf = &g_flag;
            while (*vf == 0) __nanosleep(32);
        }
    }
    __syncthreads();
    __threadfence();                                       // acquire all g_pk

    // ---- Phase B: 64-neighbor scalar gather -> n_mean; closed-form block loss ----
    float ns = 0.0f, nc = 0.0f;
    if (2 * lane < nb)     { const float2 v = g_pk[jj.x]; ns += v.x; nc += v.y; }
    if (2 * lane + 1 < nb) { const float2 v = g_pk[jj.y]; ns += v.x; nc += v.y; }
    ns = warp_sum(ns);
    nc = warp_sum(nc);

    // ---- Per-CTA partial (bce, sup, gl, val) ----
    __shared__ float4 shp[4];
    __shared__ int s_last;
    if (lane == 0) {
        const float m  = ns / fmaxf(nc, 1.0f);
        const float q  = (float)cnt_q;
        const float sq = p2 - 2.0f * m * p1 + q * m * m;   // Σ_unc (p-m)²
        const bool valid = (q > 0.0f) && (nc > 0.0f);
        shp[wid] = make_float4(bce_s, (float)cnt_s,
                               valid ? (sq / fmaxf(q, 1.0f)) : 0.0f,
                               valid ? 1.0f : 0.0f);
    }
    __syncthreads();
    if (tid == 0) {
        float4 r = shp[0];
#pragma unroll
        for (int i = 1; i < 4; i++) { r.x += shp[i].x; r.y += shp[i].y; r.z += shp[i].z; r.w += shp[i].w; }
        g_cta[blockIdx.x] = r;
        __threadfence();
        s_last = (atomicAdd(&g_done, 1) == GRID - 1) ? 1 : 0;
    }
    __syncthreads();
    if (!s_last) return;

    // ---- Last CTA: reduce 1024 float4 (16 KB, L2-hot, MLP-batched) + reset state ----
    __threadfence();
    float a = 0.f, bb = 0.f, c = 0.f, d = 0.f;
#pragma unroll
    for (int i = 0; i < GRID / CTA; i++) {                 // 8 LDG.128 per thread
        const float4 r = g_cta[i * CTA + tid];
        a += r.x; bb += r.y; c += r.z; d += r.w;
    }
    a = warp_sum(a); bb = warp_sum(bb); c = warp_sum(c); d = warp_sum(d);
    __shared__ float fin[4][4];
    if (lane == 0) { fin[0][wid] = a; fin[1][wid] = bb; fin[2][wid] = c; fin[3][wid] = d; }
    __syncthreads();
    if (tid == 0) {
        float A = 0.f, B = 0.f, C = 0.f, D = 0.f;
#pragma unroll
        for (int i = 0; i < 4; i++) { A += fin[0][i]; B += fin[1][i]; C += fin[2][i]; D += fin[3][i]; }
        const float loss_sup   = (B > 0.0f) ? (A / fmaxf(B, 1.0f)) : 0.0f;
        const float loss_graph = C / fmaxf(D, 1.0f);
        out[0] = loss_sup + 0.3f * loss_graph;
        g_bar  = 0;       // reset barrier + counters for next graph replay
        g_flag = 0;
        g_done = 0;
    }
}

extern "C" void kernel_launch(void* const* d_in, const int* in_sizes, int n_in,
                              void* d_out, int out_size) {
    const float4* x4   = (const float4*)d_in[0];  // logits   [524288] f32
    const float4* t4   = (const float4*)d_in[1];  // targets  [524288] f32
    const uint4*  s4   = (const uint4*)d_in[2];   // sup_mask  (4-byte bool)
    const uint4*  i4   = (const uint4*)d_in[3];   // ignore_mask
    const uint2*  kvi2 = (const uint2*)d_in[4];   // kv_indices [4096*64] as uint2
    const int*    kvn  = (const int*)d_in[5];     // kv_num_blocks [4096]
    (void)in_sizes; (void)n_in; (void)out_size;

    fused<<<GRID, CTA>>>(x4, t4, s4, i4, kvi2, kvn, (float*)d_out);
}